// round 6
// baseline (speedup 1.0000x reference)
#include <cuda_runtime.h>
#include <math.h>
#include <stdint.h>

// Problem shape (fixed by the dataset)
#define BATCH   4
#define S_LEN   2048
#define DMODEL  1024
#define NHEAD   16
#define HD      64
#define MTOK    (BATCH * S_LEN)        // 8192 token rows

// ---------------------------------------------------------------------------
// Scratch (device globals: allocation-free)
// ---------------------------------------------------------------------------
__device__ __align__(16) uint32_t g_x_t[(size_t)MTOK * DMODEL];
__device__ __align__(16) uint32_t g_wqkv_t[(size_t)DMODEL * 3 * DMODEL];
__device__ __align__(16) uint32_t g_wproj_t[(size_t)DMODEL * DMODEL];
__device__ __align__(16) float    g_qkv[(size_t)MTOK * 3 * DMODEL];
__device__ __align__(16) uint32_t g_attn[(size_t)MTOK * DMODEL];

__device__ __forceinline__ uint32_t f32_to_tf32(float v) {
    uint32_t b;
    asm("cvt.rna.tf32.f32 %0, %1;" : "=r"(b) : "f"(v));
    return b;
}

__device__ __forceinline__ void mma_tf32(float* c, const uint32_t* a,
                                         const uint32_t* b) {
    asm volatile(
        "mma.sync.aligned.m16n8k8.row.col.f32.tf32.tf32.f32 "
        "{%0,%1,%2,%3}, {%4,%5,%6,%7}, {%8,%9}, {%0,%1,%2,%3};"
        : "+f"(c[0]), "+f"(c[1]), "+f"(c[2]), "+f"(c[3])
        : "r"(a[0]), "r"(a[1]), "r"(a[2]), "r"(a[3]), "r"(b[0]), "r"(b[1]));
}

__device__ __forceinline__ uint32_t smem_u32(const void* p) {
    uint32_t a;
    asm("{ .reg .u64 t; cvta.to.shared.u64 t, %1; cvt.u32.u64 %0, t; }"
        : "=r"(a) : "l"(p));
    return a;
}
__device__ __forceinline__ void cp_async16(uint32_t dst, const void* src) {
    asm volatile("cp.async.cg.shared.global [%0], [%1], 16;"
                 :: "r"(dst), "l"(src));
}
#define CP_COMMIT()  asm volatile("cp.async.commit_group;" ::: "memory")
#define CP_WAIT1()   asm volatile("cp.async.wait_group 1;" ::: "memory")

// ---------------------------------------------------------------------------
// tf32 tensor-core GEMM, cp.async 3-stage pipeline, 2 CTAs/SM.
// C[M,N] = A[M,K] @ B[K,N] + bias[N]
// Block 128x128, BK=16, 128 threads, 4 warps (2m x 2n), warp tile 64x64.
// As: m-major [128][20] (pad 4 -> frag bank = 20g+q, conflict-free)
// Bs: k-major [16][136] (pad 8 -> frag bank = 8q+g, conflict-free)
// ---------------------------------------------------------------------------
#define GBM 128
#define GBN 128
#define GBK 16
#define ASTR 20
#define BSTR 136
#define A_TW (128 * ASTR)            // 2560 words
#define B_TW (GBK * BSTR)            // 2176 words
#define STG_W (A_TW + B_TW)          // 4736 words
#define GEMM_SMEM_BYTES (3 * STG_W * 4)   // 56832 B

__global__ __launch_bounds__(128, 2) void tf32_gemm_kernel(
    const uint32_t* __restrict__ A, const uint32_t* __restrict__ B,
    const float* __restrict__ bias, float* __restrict__ C,
    int M, int N, int K)
{
    extern __shared__ uint32_t smw[];
    const uint32_t smb = smem_u32(smw);

    const int tid  = threadIdx.x;
    const int wid  = tid >> 5;
    const int lane = tid & 31;
    const int g = lane >> 2;          // 0..7
    const int q = lane & 3;           // 0..3

    const int wm = (wid & 1) << 6;    // 0 or 64
    const int wn = (wid >> 1) << 6;   // 0 or 64

    const int bm = blockIdx.y * GBM;
    const int bn = blockIdx.x * GBN;
    const int NT = K / GBK;

    // cp.async task assignments (128 threads)
    // A: thread tid copies row tid (16 words = 4 x cp16)
    // B: b_kr = tid>>5 (0..3, +4 each r), b_ch = (tid&31)*4
    const int b_kr = tid >> 5;
    const int b_ch = (lane) << 2;

    auto issue = [&](int s, int kt) {
        uint32_t sb = smb + (uint32_t)(s * STG_W) * 4;
        const uint32_t* Arow = A + (size_t)(bm + tid) * K + kt * GBK;
        #pragma unroll
        for (int c = 0; c < 4; c++)
            cp_async16(sb + (uint32_t)(tid * ASTR + (c << 2)) * 4, Arow + (c << 2));
        uint32_t bb = sb + (uint32_t)A_TW * 4;
        #pragma unroll
        for (int r = 0; r < 4; r++) {
            int kr = b_kr + (r << 2);
            cp_async16(bb + (uint32_t)(kr * BSTR + b_ch) * 4,
                       B + (size_t)(kt * GBK + kr) * N + bn + b_ch);
        }
    };

    float acc[4][8][4];
    #pragma unroll
    for (int mi = 0; mi < 4; mi++)
        #pragma unroll
        for (int ni = 0; ni < 8; ni++)
            #pragma unroll
            for (int r = 0; r < 4; r++) acc[mi][ni][r] = 0.0f;

    issue(0, 0); CP_COMMIT();
    issue(1, 1); CP_COMMIT();

    for (int kt = 0; kt < NT; kt++) {
        CP_WAIT1();
        __syncthreads();
        if (kt + 2 < NT) issue((kt + 2) % 3, kt + 2);
        CP_COMMIT();

        const uint32_t* As = smw + (kt % 3) * STG_W;
        const uint32_t* Bs = As + A_TW;

        // load BOTH k8 fragment sets up front, then 64 independent MMAs
        uint32_t af[2][4][4], bf[2][8][2];
        #pragma unroll
        for (int h = 0; h < 2; h++) {
            const int k8 = h << 3;
            #pragma unroll
            for (int mi = 0; mi < 4; mi++) {
                const uint32_t* ar = As + (wm + (mi << 4) + g) * ASTR + k8 + q;
                af[h][mi][0] = ar[0];
                af[h][mi][1] = ar[8 * ASTR];
                af[h][mi][2] = ar[4];
                af[h][mi][3] = ar[8 * ASTR + 4];
            }
            #pragma unroll
            for (int ni = 0; ni < 8; ni++) {
                const uint32_t* br = Bs + (k8 + q) * BSTR + wn + (ni << 3) + g;
                bf[h][ni][0] = br[0];
                bf[h][ni][1] = br[4 * BSTR];
            }
        }
        #pragma unroll
        for (int h = 0; h < 2; h++)
            #pragma unroll
            for (int mi = 0; mi < 4; mi++)
                #pragma unroll
                for (int ni = 0; ni < 8; ni++)
                    mma_tf32(acc[mi][ni], af[h][mi], bf[h][ni]);
    }

    // epilogue
    #pragma unroll
    for (int mi = 0; mi < 4; mi++) {
        int m = bm + wm + (mi << 4) + g;
        #pragma unroll
        for (int ni = 0; ni < 8; ni++) {
            int n = bn + wn + (ni << 3) + (q << 1);
            float2 bb = *(const float2*)&bias[n];
            float2 o0, o1;
            o0.x = acc[mi][ni][0] + bb.x;
            o0.y = acc[mi][ni][1] + bb.y;
            o1.x = acc[mi][ni][2] + bb.x;
            o1.y = acc[mi][ni][3] + bb.y;
            *(float2*)&C[(size_t)m * N + n]       = o0;
            *(float2*)&C[(size_t)(m + 8) * N + n] = o1;
        }
    }
}

// ---------------------------------------------------------------------------
// Elementwise fp32 -> tf32 (rna) conversion
// ---------------------------------------------------------------------------
__global__ void cvt_tf32_kernel(const float4* __restrict__ src,
                                uint4* __restrict__ dst, int n4)
{
    int i = blockIdx.x * blockDim.x + threadIdx.x;
    if (i < n4) {
        float4 v = src[i];
        uint4 o;
        o.x = f32_to_tf32(v.x); o.y = f32_to_tf32(v.y);
        o.z = f32_to_tf32(v.z); o.w = f32_to_tf32(v.w);
        dst[i] = o;
    }
}

// ---------------------------------------------------------------------------
// Flash attention on tensor cores (tf32 mma.sync), causal. (unchanged)
// ---------------------------------------------------------------------------
#define AQS 68
#define AVS 72
#define ATTN_SMEM_BYTES ((64*AQS*3 + 64*AVS) * 4)

__global__ __launch_bounds__(128) void attn_mma_kernel()
{
    extern __shared__ uint32_t smu[];
    uint32_t* Qs = smu;
    uint32_t* Ks = Qs + 64 * AQS;
    uint32_t* Vs = Ks + 64 * AQS;
    uint32_t* Ps = Vs + 64 * AVS;

    const int tid  = threadIdx.x;
    const int wid  = tid >> 5;
    const int lane = tid & 31;
    const int g = lane >> 2;
    const int q = lane & 3;

    const int qt = blockIdx.x;
    const int bh = blockIdx.y;
    const int b  = bh >> 4;
    const int h  = bh & (NHEAD - 1);

    const int q0 = qt * 64;
    const int qr = wid << 4;
    const float NEG = -1e30f;

    for (int i = tid; i < 1024; i += 128) {
        int row = i >> 4, c4 = (i & 15) << 2;
        float4 v = *(const float4*)(g_qkv
            + (size_t)(b * S_LEN + q0 + row) * (3 * DMODEL) + h * HD + c4);
        uint4 o;
        o.x = f32_to_tf32(v.x); o.y = f32_to_tf32(v.y);
        o.z = f32_to_tf32(v.z); o.w = f32_to_tf32(v.w);
        *(uint4*)&Qs[row * AQS + c4] = o;
    }

    float O[8][4];
    #pragma unroll
    for (int ni = 0; ni < 8; ni++)
        #pragma unroll
        for (int r = 0; r < 4; r++) O[ni][r] = 0.0f;
    float mrow0 = NEG, mrow1 = NEG, lrow0 = 0.0f, lrow1 = 0.0f;

    for (int kt = 0; kt <= qt; kt++) {
        const int k0 = kt * 64;
        __syncthreads();
        for (int i = tid; i < 1024; i += 128) {
            int row = i >> 4, c4 = (i & 15) << 2;
            const float* base = g_qkv
                + (size_t)(b * S_LEN + k0 + row) * (3 * DMODEL)
                + DMODEL + h * HD + c4;
            float4 kv = *(const float4*)base;
            float4 vv = *(const float4*)(base + DMODEL);
            uint4 ok, ov;
            ok.x = f32_to_tf32(kv.x); ok.y = f32_to_tf32(kv.y);
            ok.z = f32_to_tf32(kv.z); ok.w = f32_to_tf32(kv.w);
            ov.x = f32_to_tf32(vv.x); ov.y = f32_to_tf32(vv.y);
            ov.z = f32_to_tf32(vv.z); ov.w = f32_to_tf32(vv.w);
            *(uint4*)&Ks[row * AQS + c4] = ok;
            *(uint4*)&Vs[row * AVS + c4] = ov;
        }
        __syncthreads();

        float s[8][4];
        #pragma unroll
        for (int ni = 0; ni < 8; ni++)
            #pragma unroll
            for (int r = 0; r < 4; r++) s[ni][r] = 0.0f;

        #pragma unroll
        for (int k8 = 0; k8 < 64; k8 += 8) {
            uint32_t a[4];
            a[0] = Qs[(qr + g) * AQS + k8 + q];
            a[1] = Qs[(qr + g + 8) * AQS + k8 + q];
            a[2] = Qs[(qr + g) * AQS + k8 + q + 4];
            a[3] = Qs[(qr + g + 8) * AQS + k8 + q + 4];
            #pragma unroll
            for (int ni = 0; ni < 8; ni++) {
                uint32_t bb[2];
                bb[0] = Ks[(ni * 8 + g) * AQS + k8 + q];
                bb[1] = Ks[(ni * 8 + g) * AQS + k8 + q + 4];
                mma_tf32(s[ni], a, bb);
            }
        }

        #pragma unroll
        for (int ni = 0; ni < 8; ni++)
            #pragma unroll
            for (int r = 0; r < 4; r++) s[ni][r] *= 0.125f;
        if (kt == qt) {
            int r0 = qr + g, r1 = qr + g + 8;
            #pragma unroll
            for (int ni = 0; ni < 8; ni++) {
                int c = ni * 8 + (q << 1);
                if (c > r0)     s[ni][0] = NEG;
                if (c + 1 > r0) s[ni][1] = NEG;
                if (c > r1)     s[ni][2] = NEG;
                if (c + 1 > r1) s[ni][3] = NEG;
            }
        }

        float mx0 = NEG, mx1 = NEG;
        #pragma unroll
        for (int ni = 0; ni < 8; ni++) {
            mx0 = fmaxf(mx0, fmaxf(s[ni][0], s[ni][1]));
            mx1 = fmaxf(mx1, fmaxf(s[ni][2], s[ni][3]));
        }
        mx0 = fmaxf(mx0, __shfl_xor_sync(0xffffffffu, mx0, 1));
        mx0 = fmaxf(mx0, __shfl_xor_sync(0xffffffffu, mx0, 2));
        mx1 = fmaxf(mx1, __shfl_xor_sync(0xffffffffu, mx1, 1));
        mx1 = fmaxf(mx1, __shfl_xor_sync(0xffffffffu, mx1, 2));

        float mn0 = fmaxf(mrow0, mx0), mn1 = fmaxf(mrow1, mx1);
        float corr0 = __expf(mrow0 - mn0), corr1 = __expf(mrow1 - mn1);
        float sum0 = 0.0f, sum1 = 0.0f;
        #pragma unroll
        for (int ni = 0; ni < 8; ni++) {
            s[ni][0] = __expf(s[ni][0] - mn0);
            s[ni][1] = __expf(s[ni][1] - mn0);
            s[ni][2] = __expf(s[ni][2] - mn1);
            s[ni][3] = __expf(s[ni][3] - mn1);
            sum0 += s[ni][0] + s[ni][1];
            sum1 += s[ni][2] + s[ni][3];
        }
        sum0 += __shfl_xor_sync(0xffffffffu, sum0, 1);
        sum0 += __shfl_xor_sync(0xffffffffu, sum0, 2);
        sum1 += __shfl_xor_sync(0xffffffffu, sum1, 1);
        sum1 += __shfl_xor_sync(0xffffffffu, sum1, 2);
        lrow0 = lrow0 * corr0 + sum0;
        lrow1 = lrow1 * corr1 + sum1;
        mrow0 = mn0; mrow1 = mn1;
        #pragma unroll
        for (int ni = 0; ni < 8; ni++) {
            O[ni][0] *= corr0; O[ni][1] *= corr0;
            O[ni][2] *= corr1; O[ni][3] *= corr1;
        }

        #pragma unroll
        for (int ni = 0; ni < 8; ni++) {
            int c = ni * 8 + (q << 1);
            uint2 p0, p1;
            p0.x = f32_to_tf32(s[ni][0]); p0.y = f32_to_tf32(s[ni][1]);
            p1.x = f32_to_tf32(s[ni][2]); p1.y = f32_to_tf32(s[ni][3]);
            *(uint2*)&Ps[(qr + g) * AQS + c]     = p0;
            *(uint2*)&Ps[(qr + g + 8) * AQS + c] = p1;
        }
        __syncwarp();

        #pragma unroll
        for (int k8 = 0; k8 < 64; k8 += 8) {
            uint32_t a[4];
            a[0] = Ps[(qr + g) * AQS + k8 + q];
            a[1] = Ps[(qr + g + 8) * AQS + k8 + q];
            a[2] = Ps[(qr + g) * AQS + k8 + q + 4];
            a[3] = Ps[(qr + g + 8) * AQS + k8 + q + 4];
            #pragma unroll
            for (int ni = 0; ni < 8; ni++) {
                uint32_t bb[2];
                bb[0] = Vs[(k8 + q) * AVS + ni * 8 + g];
                bb[1] = Vs[(k8 + q + 4) * AVS + ni * 8 + g];
                mma_tf32(O[ni], a, bb);
            }
        }
    }

    float inv0 = 1.0f / lrow0, inv1 = 1.0f / lrow1;
    int r0 = q0 + qr + g, r1 = r0 + 8;
    uint32_t* d0 = g_attn + (size_t)(b * S_LEN + r0) * DMODEL + h * HD;
    uint32_t* d1 = g_attn + (size_t)(b * S_LEN + r1) * DMODEL + h * HD;
    #pragma unroll
    for (int ni = 0; ni < 8; ni++) {
        int c = ni * 8 + (q << 1);
        uint2 o0, o1;
        o0.x = f32_to_tf32(O[ni][0] * inv0); o0.y = f32_to_tf32(O[ni][1] * inv0);
        o1.x = f32_to_tf32(O[ni][2] * inv1); o1.y = f32_to_tf32(O[ni][3] * inv1);
        *(uint2*)&d0[c] = o0;
        *(uint2*)&d1[c] = o1;
    }
}

// ---------------------------------------------------------------------------
// kernel_launch: x, w_qkv, b_qkv, w_proj, b_proj
// ---------------------------------------------------------------------------
extern "C" void kernel_launch(void* const* d_in, const int* in_sizes, int n_in,
                              void* d_out, int out_size)
{
    const float* x      = (const float*)d_in[0];
    const float* w_qkv  = (const float*)d_in[1];
    const float* b_qkv  = (const float*)d_in[2];
    const float* w_proj = (const float*)d_in[3];
    const float* b_proj = (const float*)d_in[4];
    float* out = (float*)d_out;

    void *x_t, *wqkv_t, *wproj_t, *qkv, *attn;
    cudaGetSymbolAddress(&x_t, g_x_t);
    cudaGetSymbolAddress(&wqkv_t, g_wqkv_t);
    cudaGetSymbolAddress(&wproj_t, g_wproj_t);
    cudaGetSymbolAddress(&qkv, g_qkv);
    cudaGetSymbolAddress(&attn, g_attn);

    cudaFuncSetAttribute(tf32_gemm_kernel,
                         cudaFuncAttributeMaxDynamicSharedMemorySize,
                         GEMM_SMEM_BYTES);
    cudaFuncSetAttribute(attn_mma_kernel,
                         cudaFuncAttributeMaxDynamicSharedMemorySize,
                         ATTN_SMEM_BYTES);

    // 0) precision-preserving tf32 conversions (cvt.rna)
    {
        int n4x = MTOK * DMODEL / 4;
        cvt_tf32_kernel<<<(n4x + 255) / 256, 256>>>((const float4*)x, (uint4*)x_t, n4x);
        int n4q = DMODEL * 3 * DMODEL / 4;
        cvt_tf32_kernel<<<(n4q + 255) / 256, 256>>>((const float4*)w_qkv, (uint4*)wqkv_t, n4q);
        int n4p = DMODEL * DMODEL / 4;
        cvt_tf32_kernel<<<(n4p + 255) / 256, 256>>>((const float4*)w_proj, (uint4*)wproj_t, n4p);
    }

    // 1) QKV projection: [8192,1024] @ [1024,3072] + b
    {
        dim3 grid(3 * DMODEL / GBN, MTOK / GBM);
        tf32_gemm_kernel<<<grid, 128, GEMM_SMEM_BYTES>>>(
            (const uint32_t*)x_t, (const uint32_t*)wqkv_t, b_qkv, (float*)qkv,
            MTOK, 3 * DMODEL, DMODEL);
    }

    // 2) causal flash attention on tensor cores
    {
        dim3 grid(S_LEN / 64, BATCH * NHEAD);
        attn_mma_kernel<<<grid, 128, ATTN_SMEM_BYTES>>>();
    }

    // 3) output projection: [8192,1024] @ [1024,1024] + b
    {
        dim3 grid(DMODEL / GBN, MTOK / GBM);
        tf32_gemm_kernel<<<grid, 128, GEMM_SMEM_BYTES>>>(
            (const uint32_t*)attn, (const uint32_t*)wproj_t, b_proj, out,
            MTOK, DMODEL, DMODEL);
    }
}

// round 8
// speedup vs baseline: 1.0862x; 1.0862x over previous
#include <cuda_runtime.h>
#include <math.h>
#include <stdint.h>

// Problem shape (fixed by the dataset)
#define BATCH   4
#define S_LEN   2048
#define DMODEL  1024
#define NHEAD   16
#define HD      64
#define MTOK    (BATCH * S_LEN)        // 8192 token rows

// ---------------------------------------------------------------------------
// Scratch (device globals: allocation-free)
// ---------------------------------------------------------------------------
__device__ __align__(16) float g_qkv[(size_t)MTOK * 3 * DMODEL];   // fp32 qkv
__device__ __align__(16) float g_attn[(size_t)MTOK * DMODEL];      // fp32 attn out

__device__ __forceinline__ uint32_t f32_to_tf32(float v) {
    uint32_t b;
    asm("cvt.rna.tf32.f32 %0, %1;" : "=r"(b) : "f"(v));
    return b;
}

__device__ __forceinline__ void mma_tf32(float* c, const uint32_t* a,
                                         const uint32_t* b) {
    asm volatile(
        "mma.sync.aligned.m16n8k8.row.col.f32.tf32.tf32.f32 "
        "{%0,%1,%2,%3}, {%4,%5,%6,%7}, {%8,%9}, {%0,%1,%2,%3};"
        : "+f"(c[0]), "+f"(c[1]), "+f"(c[2]), "+f"(c[3])
        : "r"(a[0]), "r"(a[1]), "r"(a[2]), "r"(a[3]), "r"(b[0]), "r"(b[1]));
}

__device__ __forceinline__ uint32_t smem_u32(const void* p) {
    uint32_t a;
    asm("{ .reg .u64 t; cvta.to.shared.u64 t, %1; cvt.u32.u64 %0, t; }"
        : "=r"(a) : "l"(p));
    return a;
}
__device__ __forceinline__ void cp_async16(uint32_t dst, const void* src) {
    asm volatile("cp.async.cg.shared.global [%0], [%1], 16;"
                 :: "r"(dst), "l"(src));
}
#define CP_COMMIT()  asm volatile("cp.async.commit_group;" ::: "memory")
#define CP_WAIT1()   asm volatile("cp.async.wait_group 1;" ::: "memory")

// ---------------------------------------------------------------------------
// tf32 tensor-core GEMM, fp32 operands (in-register cvt.rna on fragments).
// C[M,N] = A[M,K] @ B[K,N] + bias[N]
// Block 128x256, BK=16, 256 threads, 8 warps (2m x 4n), warp tile 64x64.
// 3-stage cp.async pipeline (round-5 proven structure).
// As: m-major [128][20]  Bs: k-major [16][264]
// ---------------------------------------------------------------------------
#define GBM 128
#define GBN 256
#define GBK 16
#define ASTR 20
#define BSTR 264
#define A_TW (128 * ASTR)            // 2560 words
#define B_TW (GBK * BSTR)            // 4224 words
#define STG_W (A_TW + B_TW)          // 6784 words
#define GEMM_SMEM_BYTES (3 * STG_W * 4)   // 81408 B

__global__ __launch_bounds__(256, 1) void tf32_gemm_kernel(
    const float* __restrict__ A, const float* __restrict__ B,
    const float* __restrict__ bias, float* __restrict__ C,
    int M, int N, int K)
{
    extern __shared__ float smw[];
    const uint32_t smb = smem_u32(smw);

    const int tid  = threadIdx.x;
    const int wid  = tid >> 5;
    const int lane = tid & 31;
    const int g = lane >> 2;          // 0..7
    const int q = lane & 3;           // 0..3

    const int wm = (wid & 1) << 6;    // 0 or 64
    const int wn = (wid >> 1) << 6;   // 0,64,128,192

    const int bm = blockIdx.y * GBM;
    const int bn = blockIdx.x * GBN;
    const int NT = K / GBK;

    const int a_row = tid >> 2;           // 0..63 (+64 for r=1)
    const int a_ch  = (tid & 3) << 2;     // 0,4,8,12
    const int b_kr  = tid >> 6;           // 0..3 (+4..12)
    const int b_ch  = (tid & 63) << 2;    // 0..252

    auto issue = [&](int s, int kt) {
        uint32_t sb = smb + (uint32_t)(s * STG_W) * 4;
        #pragma unroll
        for (int r = 0; r < 2; r++) {
            int row = a_row + (r << 6);
            cp_async16(sb + (uint32_t)(row * ASTR + a_ch) * 4,
                       A + (size_t)(bm + row) * K + kt * GBK + a_ch);
        }
        uint32_t bb = sb + (uint32_t)A_TW * 4;
        #pragma unroll
        for (int r = 0; r < 4; r++) {
            int kr = b_kr + (r << 2);
            cp_async16(bb + (uint32_t)(kr * BSTR + b_ch) * 4,
                       B + (size_t)(kt * GBK + kr) * N + bn + b_ch);
        }
    };

    float acc[4][8][4];
    #pragma unroll
    for (int mi = 0; mi < 4; mi++)
        #pragma unroll
        for (int ni = 0; ni < 8; ni++)
            #pragma unroll
            for (int r = 0; r < 4; r++) acc[mi][ni][r] = 0.0f;

    issue(0, 0); CP_COMMIT();
    issue(1, 1); CP_COMMIT();

    for (int kt = 0; kt < NT; kt++) {
        CP_WAIT1();
        __syncthreads();
        if (kt + 2 < NT) issue((kt + 2) % 3, kt + 2);
        CP_COMMIT();

        const float* As = smw + (kt % 3) * STG_W;
        const float* Bs = As + A_TW;

        #pragma unroll
        for (int k8 = 0; k8 < GBK; k8 += 8) {
            uint32_t af[4][4], bf[8][2];
            #pragma unroll
            for (int mi = 0; mi < 4; mi++) {
                const float* ar = As + (wm + (mi << 4) + g) * ASTR + k8 + q;
                af[mi][0] = f32_to_tf32(ar[0]);
                af[mi][1] = f32_to_tf32(ar[8 * ASTR]);
                af[mi][2] = f32_to_tf32(ar[4]);
                af[mi][3] = f32_to_tf32(ar[8 * ASTR + 4]);
            }
            #pragma unroll
            for (int ni = 0; ni < 8; ni++) {
                const float* br = Bs + (k8 + q) * BSTR + wn + (ni << 3) + g;
                bf[ni][0] = f32_to_tf32(br[0]);
                bf[ni][1] = f32_to_tf32(br[4 * BSTR]);
            }
            #pragma unroll
            for (int mi = 0; mi < 4; mi++)
                #pragma unroll
                for (int ni = 0; ni < 8; ni++)
                    mma_tf32(acc[mi][ni], af[mi], bf[ni]);
        }
    }

    // epilogue
    #pragma unroll
    for (int mi = 0; mi < 4; mi++) {
        int m = bm + wm + (mi << 4) + g;
        #pragma unroll
        for (int ni = 0; ni < 8; ni++) {
            int n = bn + wn + (ni << 3) + (q << 1);
            float2 bb = *(const float2*)&bias[n];
            float2 o0, o1;
            o0.x = acc[mi][ni][0] + bb.x;
            o0.y = acc[mi][ni][1] + bb.y;
            o1.x = acc[mi][ni][2] + bb.x;
            o1.y = acc[mi][ni][3] + bb.y;
            *(float2*)&C[(size_t)m * N + n]       = o0;
            *(float2*)&C[(size_t)(m + 8) * N + n] = o1;
        }
    }
}

// ---------------------------------------------------------------------------
// Flash attention on tensor cores (tf32 mma.sync), causal.
// EXACT round-5/6 passing version (synchronous K/V load), except the final
// store writes fp32 instead of tf32.
// Block = 64 q-rows, 4 warps. smem: Qs/Ks/Ps stride 68 (tf32), Vs stride 72.
// ---------------------------------------------------------------------------
#define AQS 68
#define AVS 72
#define ATTN_SMEM_BYTES ((64*AQS*3 + 64*AVS) * 4)

__global__ __launch_bounds__(128) void attn_mma_kernel()
{
    extern __shared__ uint32_t smu[];
    uint32_t* Qs = smu;
    uint32_t* Ks = Qs + 64 * AQS;
    uint32_t* Vs = Ks + 64 * AQS;
    uint32_t* Ps = Vs + 64 * AVS;

    const int tid  = threadIdx.x;
    const int wid  = tid >> 5;
    const int lane = tid & 31;
    const int g = lane >> 2;
    const int q = lane & 3;

    const int qt = blockIdx.x;
    const int bh = blockIdx.y;
    const int b  = bh >> 4;
    const int h  = bh & (NHEAD - 1);

    const int q0 = qt * 64;
    const int qr = wid << 4;
    const float NEG = -1e30f;

    for (int i = tid; i < 1024; i += 128) {
        int row = i >> 4, c4 = (i & 15) << 2;
        float4 v = *(const float4*)(g_qkv
            + (size_t)(b * S_LEN + q0 + row) * (3 * DMODEL) + h * HD + c4);
        uint4 o;
        o.x = f32_to_tf32(v.x); o.y = f32_to_tf32(v.y);
        o.z = f32_to_tf32(v.z); o.w = f32_to_tf32(v.w);
        *(uint4*)&Qs[row * AQS + c4] = o;
    }

    float O[8][4];
    #pragma unroll
    for (int ni = 0; ni < 8; ni++)
        #pragma unroll
        for (int r = 0; r < 4; r++) O[ni][r] = 0.0f;
    float mrow0 = NEG, mrow1 = NEG, lrow0 = 0.0f, lrow1 = 0.0f;

    for (int kt = 0; kt <= qt; kt++) {
        const int k0 = kt * 64;
        __syncthreads();
        for (int i = tid; i < 1024; i += 128) {
            int row = i >> 4, c4 = (i & 15) << 2;
            const float* base = g_qkv
                + (size_t)(b * S_LEN + k0 + row) * (3 * DMODEL)
                + DMODEL + h * HD + c4;
            float4 kv = *(const float4*)base;
            float4 vv = *(const float4*)(base + DMODEL);
            uint4 ok, ov;
            ok.x = f32_to_tf32(kv.x); ok.y = f32_to_tf32(kv.y);
            ok.z = f32_to_tf32(kv.z); ok.w = f32_to_tf32(kv.w);
            ov.x = f32_to_tf32(vv.x); ov.y = f32_to_tf32(vv.y);
            ov.z = f32_to_tf32(vv.z); ov.w = f32_to_tf32(vv.w);
            *(uint4*)&Ks[row * AQS + c4] = ok;
            *(uint4*)&Vs[row * AVS + c4] = ov;
        }
        __syncthreads();

        float s[8][4];
        #pragma unroll
        for (int ni = 0; ni < 8; ni++)
            #pragma unroll
            for (int r = 0; r < 4; r++) s[ni][r] = 0.0f;

        #pragma unroll
        for (int k8 = 0; k8 < 64; k8 += 8) {
            uint32_t a[4];
            a[0] = Qs[(qr + g) * AQS + k8 + q];
            a[1] = Qs[(qr + g + 8) * AQS + k8 + q];
            a[2] = Qs[(qr + g) * AQS + k8 + q + 4];
            a[3] = Qs[(qr + g + 8) * AQS + k8 + q + 4];
            #pragma unroll
            for (int ni = 0; ni < 8; ni++) {
                uint32_t bb[2];
                bb[0] = Ks[(ni * 8 + g) * AQS + k8 + q];
                bb[1] = Ks[(ni * 8 + g) * AQS + k8 + q + 4];
                mma_tf32(s[ni], a, bb);
            }
        }

        #pragma unroll
        for (int ni = 0; ni < 8; ni++)
            #pragma unroll
            for (int r = 0; r < 4; r++) s[ni][r] *= 0.125f;
        if (kt == qt) {
            int r0 = qr + g, r1 = qr + g + 8;
            #pragma unroll
            for (int ni = 0; ni < 8; ni++) {
                int c = ni * 8 + (q << 1);
                if (c > r0)     s[ni][0] = NEG;
                if (c + 1 > r0) s[ni][1] = NEG;
                if (c > r1)     s[ni][2] = NEG;
                if (c + 1 > r1) s[ni][3] = NEG;
            }
        }

        float mx0 = NEG, mx1 = NEG;
        #pragma unroll
        for (int ni = 0; ni < 8; ni++) {
            mx0 = fmaxf(mx0, fmaxf(s[ni][0], s[ni][1]));
            mx1 = fmaxf(mx1, fmaxf(s[ni][2], s[ni][3]));
        }
        mx0 = fmaxf(mx0, __shfl_xor_sync(0xffffffffu, mx0, 1));
        mx0 = fmaxf(mx0, __shfl_xor_sync(0xffffffffu, mx0, 2));
        mx1 = fmaxf(mx1, __shfl_xor_sync(0xffffffffu, mx1, 1));
        mx1 = fmaxf(mx1, __shfl_xor_sync(0xffffffffu, mx1, 2));

        float mn0 = fmaxf(mrow0, mx0), mn1 = fmaxf(mrow1, mx1);
        float corr0 = __expf(mrow0 - mn0), corr1 = __expf(mrow1 - mn1);
        float sum0 = 0.0f, sum1 = 0.0f;
        #pragma unroll
        for (int ni = 0; ni < 8; ni++) {
            s[ni][0] = __expf(s[ni][0] - mn0);
            s[ni][1] = __expf(s[ni][1] - mn0);
            s[ni][2] = __expf(s[ni][2] - mn1);
            s[ni][3] = __expf(s[ni][3] - mn1);
            sum0 += s[ni][0] + s[ni][1];
            sum1 += s[ni][2] + s[ni][3];
        }
        sum0 += __shfl_xor_sync(0xffffffffu, sum0, 1);
        sum0 += __shfl_xor_sync(0xffffffffu, sum0, 2);
        sum1 += __shfl_xor_sync(0xffffffffu, sum1, 1);
        sum1 += __shfl_xor_sync(0xffffffffu, sum1, 2);
        lrow0 = lrow0 * corr0 + sum0;
        lrow1 = lrow1 * corr1 + sum1;
        mrow0 = mn0; mrow1 = mn1;
        #pragma unroll
        for (int ni = 0; ni < 8; ni++) {
            O[ni][0] *= corr0; O[ni][1] *= corr0;
            O[ni][2] *= corr1; O[ni][3] *= corr1;
        }

        #pragma unroll
        for (int ni = 0; ni < 8; ni++) {
            int c = ni * 8 + (q << 1);
            uint2 p0, p1;
            p0.x = f32_to_tf32(s[ni][0]); p0.y = f32_to_tf32(s[ni][1]);
            p1.x = f32_to_tf32(s[ni][2]); p1.y = f32_to_tf32(s[ni][3]);
            *(uint2*)&Ps[(qr + g) * AQS + c]     = p0;
            *(uint2*)&Ps[(qr + g + 8) * AQS + c] = p1;
        }
        __syncwarp();

        #pragma unroll
        for (int k8 = 0; k8 < 64; k8 += 8) {
            uint32_t a[4];
            a[0] = Ps[(qr + g) * AQS + k8 + q];
            a[1] = Ps[(qr + g + 8) * AQS + k8 + q];
            a[2] = Ps[(qr + g) * AQS + k8 + q + 4];
            a[3] = Ps[(qr + g + 8) * AQS + k8 + q + 4];
            #pragma unroll
            for (int ni = 0; ni < 8; ni++) {
                uint32_t bb[2];
                bb[0] = Vs[(k8 + q) * AVS + ni * 8 + g];
                bb[1] = Vs[(k8 + q + 4) * AVS + ni * 8 + g];
                mma_tf32(O[ni], a, bb);
            }
        }
    }

    // normalize + store fp32 (proj GEMM consumes fp32 directly)
    float inv0 = 1.0f / lrow0, inv1 = 1.0f / lrow1;
    int r0 = q0 + qr + g, r1 = r0 + 8;
    float* d0 = g_attn + (size_t)(b * S_LEN + r0) * DMODEL + h * HD;
    float* d1 = g_attn + (size_t)(b * S_LEN + r1) * DMODEL + h * HD;
    #pragma unroll
    for (int ni = 0; ni < 8; ni++) {
        int c = ni * 8 + (q << 1);
        float2 o0, o1;
        o0.x = O[ni][0] * inv0; o0.y = O[ni][1] * inv0;
        o1.x = O[ni][2] * inv1; o1.y = O[ni][3] * inv1;
        *(float2*)&d0[c] = o0;
        *(float2*)&d1[c] = o1;
    }
}

// ---------------------------------------------------------------------------
// kernel_launch: x, w_qkv, b_qkv, w_proj, b_proj
// ---------------------------------------------------------------------------
extern "C" void kernel_launch(void* const* d_in, const int* in_sizes, int n_in,
                              void* d_out, int out_size)
{
    const float* x      = (const float*)d_in[0];
    const float* w_qkv  = (const float*)d_in[1];
    const float* b_qkv  = (const float*)d_in[2];
    const float* w_proj = (const float*)d_in[3];
    const float* b_proj = (const float*)d_in[4];
    float* out = (float*)d_out;

    void *qkv, *attn;
    cudaGetSymbolAddress(&qkv, g_qkv);
    cudaGetSymbolAddress(&attn, g_attn);

    cudaFuncSetAttribute(tf32_gemm_kernel,
                         cudaFuncAttributeMaxDynamicSharedMemorySize,
                         GEMM_SMEM_BYTES);
    cudaFuncSetAttribute(attn_mma_kernel,
                         cudaFuncAttributeMaxDynamicSharedMemorySize,
                         ATTN_SMEM_BYTES);

    // 1) QKV projection: [8192,1024] @ [1024,3072] + b   (fp32 in, tf32 MMA)
    {
        dim3 grid(3 * DMODEL / GBN, MTOK / GBM);
        tf32_gemm_kernel<<<grid, 256, GEMM_SMEM_BYTES>>>(
            x, w_qkv, b_qkv, (float*)qkv, MTOK, 3 * DMODEL, DMODEL);
    }

    // 2) causal flash attention on tensor cores
    {
        dim3 grid(S_LEN / 64, BATCH * NHEAD);
        attn_mma_kernel<<<grid, 128, ATTN_SMEM_BYTES>>>();
    }

    // 3) output projection: [8192,1024] @ [1024,1024] + b
    {
        dim3 grid(DMODEL / GBN, MTOK / GBM);
        tf32_gemm_kernel<<<grid, 256, GEMM_SMEM_BYTES>>>(
            (const float*)attn, w_proj, b_proj, out, MTOK, DMODEL, DMODEL);
    }
}